// round 1
// baseline (speedup 1.0000x reference)
#include <cuda_runtime.h>
#include <math.h>

#define NB  4
#define CIN 256
#define PL  128
#define HH  128
#define WW  128
#define HW  16384
#define KK  9
#define CK  1152   // PL*KK

// ---- scratch (device globals: allocation-free) ----
__device__ float g_out1_nchw[NB*PL*HW];   // 33.5 MB
__device__ float g_out1_nhwc[NB*HW*PL];   // 33.5 MB
__device__ float g_ident[NB*PL*HW];       // 33.5 MB
__device__ float g_py[NB*KK*HW];
__device__ float g_px[NB*KK*HW];
__device__ float g_mk[NB*KK*HW];
__device__ float g_wOffT[CK*32];          // [ck][o<27, pad 32]
__device__ float g_wDcT[CK*PL];           // [ck][o]
__device__ float g_w3T[PL*PL];            // [i][o]

// ---------------- K0: weight transposes ----------------
__global__ void k_prep(const float* __restrict__ w_off,
                       const float* __restrict__ w_dc,
                       const float* __restrict__ w3) {
    int i = blockIdx.x * blockDim.x + threadIdx.x;
    if (i < CK*32) {
        int ck = i >> 5, o = i & 31;
        g_wOffT[i] = (o < 27) ? w_off[o*CK + ck] : 0.f;
    }
    if (i < CK*PL) {
        int ck = i >> 7, o = i & 127;
        g_wDcT[i] = w_dc[o*CK + ck];
    }
    if (i < PL*PL) {
        int r = i >> 7, o = i & 127;
        g_w3T[i] = w3[o*PL + r];
    }
}

// ---------------- K1: conv1(+bn+relu x2) and downsample(+bias+bn) ----------------
// grid (HW/64, 4, NB), block 256. by 0/1 -> out1 output halves, by 2/3 -> ident halves.
__global__ __launch_bounds__(256) void k_conv1_ds(
    const float* __restrict__ x, const float* __restrict__ w1, const float* __restrict__ wds,
    const float* __restrict__ s1a, const float* __restrict__ t1a,
    const float* __restrict__ s1b, const float* __restrict__ t1b,
    const float* __restrict__ bds, const float* __restrict__ sd, const float* __restrict__ td)
{
    __shared__ __align__(16) float sm[4352];
    float* Wsh = sm;          // [32][68]
    float* Xsh = sm + 2176;   // [32][68]

    const int t  = threadIdx.x;
    const int px = t & 15;     // position sub-tile (4 pos each)
    const int oy = t >> 4;     // output sub-tile (4 outs each)
    const int pos0 = blockIdx.x * 64;
    const int ot = blockIdx.y;
    const int b  = blockIdx.z;
    const bool isds = (ot >= 2);
    const float* w = isds ? wds : w1;
    const int o0 = (ot & 1) * 64;

    float acc[4][4];
#pragma unroll
    for (int j = 0; j < 4; j++)
#pragma unroll
        for (int k = 0; k < 4; k++) acc[j][k] = 0.f;

    const float* xb = x + (size_t)b * CIN * HW + pos0;

    for (int c0 = 0; c0 < CIN; c0 += 32) {
        for (int idx = t; idx < 2048; idx += 256) {
            int o = idx >> 5, i = idx & 31;
            Wsh[i*68 + o] = w[(o0 + o)*CIN + c0 + i];
        }
        for (int idx = t; idx < 2048; idx += 256) {
            int i = idx >> 6, p = idx & 63;
            Xsh[i*68 + p] = xb[(size_t)(c0 + i) * HW + p];
        }
        __syncthreads();
#pragma unroll
        for (int i = 0; i < 32; i++) {
            float4 wv = *(const float4*)&Wsh[i*68 + oy*4];
            float4 xv = *(const float4*)&Xsh[i*68 + px*4];
            float wr[4] = {wv.x, wv.y, wv.z, wv.w};
            float xr[4] = {xv.x, xv.y, xv.z, xv.w};
#pragma unroll
            for (int j = 0; j < 4; j++)
#pragma unroll
                for (int k = 0; k < 4; k++) acc[j][k] += wr[j] * xr[k];
        }
        __syncthreads();
    }

    if (!isds) {
#pragma unroll
        for (int j = 0; j < 4; j++) {
            int o = o0 + oy*4 + j;
            float sa = s1a[o], ta = t1a[o], sb = s1b[o], tb = t1b[o];
#pragma unroll
            for (int k = 0; k < 4; k++) {
                int p = pos0 + px*4 + k;
                float y = acc[j][k];
                y = fmaxf(y * sa + ta, 0.f);
                y = fmaxf(y * sb + tb, 0.f);
                g_out1_nchw[((size_t)(b*PL + o))*HW + p] = y;
                sm[(px*4 + k)*68 + oy*4 + j] = y;   // stage for NHWC
            }
        }
        __syncthreads();
        for (int idx = t; idx < 4096; idx += 256) {
            int p = idx >> 6, o = idx & 63;
            g_out1_nhwc[((size_t)(b*HW + pos0 + p))*PL + o0 + o] = sm[p*68 + o];
        }
    } else {
#pragma unroll
        for (int j = 0; j < 4; j++) {
            int o = o0 + oy*4 + j;
            float bb = bds[o], ss = sd[o], tt = td[o];
#pragma unroll
            for (int k = 0; k < 4; k++) {
                int p = pos0 + px*4 + k;
                float y = (acc[j][k] + bb) * ss + tt;
                g_ident[((size_t)(b*PL + o))*HW + p] = y;
            }
        }
    }
}

// ---------------- K2: offset/mask 3x3 conv -> absolute coords + sigmoid mask ----------------
// grid (HH, NB), block 128 (4 warps, each warp = 32 consecutive x).
__global__ __launch_bounds__(128) void k_offset(const float* __restrict__ b_off) {
    const int t = threadIdx.x;
    const int lane = t & 31;
    const int h = blockIdx.x;
    const int b = blockIdx.y;
    const int xx = (t >> 5) * 32 + lane;

    float acc[28];
#pragma unroll
    for (int i = 0; i < 28; i++) acc[i] = 0.f;

    const float* inb = g_out1_nchw + (size_t)b * PL * HW;

    for (int c = 0; c < PL; c++) {
        const float* row = inb + (size_t)c * HW + h * WW;
        float sv[3][3];
#pragma unroll
        for (int dy = 0; dy < 3; dy++) {
            int yy = h + dy - 1;
            float m = 0.f, lf = 0.f, rg = 0.f;
            if (yy >= 0 && yy < HH) {                    // warp-uniform branch
                const float* r2 = row + (dy - 1) * WW;
                m = r2[xx];
                lf = __shfl_up_sync(0xffffffffu, m, 1);
                if (lane == 0)  lf = (xx > 0) ? r2[xx - 1] : 0.f;
                rg = __shfl_down_sync(0xffffffffu, m, 1);
                if (lane == 31) rg = (xx < WW - 1) ? r2[xx + 1] : 0.f;
            }
            sv[dy][0] = lf; sv[dy][1] = m; sv[dy][2] = rg;
        }
#pragma unroll
        for (int k = 0; k < 9; k++) {
            float s = sv[k/3][k%3];
            const float4* wp = (const float4*)&g_wOffT[(c*9 + k) * 32];
#pragma unroll
            for (int j = 0; j < 7; j++) {
                float4 w4 = wp[j];
                acc[4*j+0] += w4.x * s;
                acc[4*j+1] += w4.y * s;
                acc[4*j+2] += w4.z * s;
                acc[4*j+3] += w4.w * s;
            }
        }
    }

    const int pos = h * WW + xx;
#pragma unroll
    for (int k = 0; k < 9; k++) {
        float dyv = acc[k]      + b_off[k];
        float dxv = acc[9 + k]  + b_off[9 + k];
        float z   = acc[18 + k] + b_off[18 + k];
        float mk  = 1.f / (1.f + expf(-z));
        int idx = (b*KK + k)*HW + pos;
        g_py[idx] = (float)(h - 1 + k/3) + dyv;
        g_px[idx] = (float)(xx - 1 + k%3) + dxv;
        g_mk[idx] = mk;
    }
}

// ---------------- K3: deform gather + deform conv + bn2/relu + conv3 + bns + residual ----------------
// grid (HW/16, NB), block 256. Dynamic smem: 16*1152 (sampled) + 16*128 (v) + 3*144 (coords).
#define SMEM3 ((16*CK + 16*PL + 3*144) * sizeof(float))

__global__ __launch_bounds__(256) void k_deform(
    const float* __restrict__ b_dc, const float* __restrict__ s2, const float* __restrict__ t2,
    const float* __restrict__ s3a, const float* __restrict__ t3a,
    const float* __restrict__ s3b, const float* __restrict__ t3b,
    float* __restrict__ out)
{
    extern __shared__ __align__(16) float smd[];
    float* s_sh = smd;                 // [16][1152]
    float* v_sh = smd + 16*CK;         // [16][128]
    float* cY   = v_sh + 16*PL;        // [144]
    float* cX   = cY + 144;
    float* cM   = cX + 144;

    const int tid  = threadIdx.x;
    const int b    = blockIdx.y;
    const int pos0 = blockIdx.x * 16;

    if (tid < 144) {
        int p = tid / 9, k = tid - 9*p;
        int idx = (b*KK + k)*HW + pos0 + p;
        cY[tid] = g_py[idx]; cX[tid] = g_px[idx]; cM[tid] = g_mk[idx];
    }
    __syncthreads();

    // Phase A: bilinear gather into shared (c = lane dim, NHWC coalesced)
    {
        const int c = tid & 127;
        const float* base = g_out1_nhwc + (size_t)b * HW * PL;
        for (int q = tid >> 7; q < 144; q += 2) {
            int p = q / 9, k = q - 9*p;
            float py = cY[q], px = cX[q], mk = cM[q];
            float fy = floorf(py), fx = floorf(px);
            float wy = py - fy, wx = px - fx;
            int y0 = (int)fy, x0 = (int)fx;
            bool y0ok = (y0 >= 0) && (y0 < HH);
            bool y1ok = (y0 + 1 >= 0) && (y0 + 1 < HH);
            bool x0ok = (x0 >= 0) && (x0 < WW);
            bool x1ok = (x0 + 1 >= 0) && (x0 + 1 < WW);
            float v00 = 0.f, v01 = 0.f, v10 = 0.f, v11 = 0.f;
            if (y0ok && x0ok) v00 = base[((size_t)(y0*WW + x0))*PL + c];
            if (y0ok && x1ok) v01 = base[((size_t)(y0*WW + x0 + 1))*PL + c];
            if (y1ok && x0ok) v10 = base[((size_t)((y0+1)*WW + x0))*PL + c];
            if (y1ok && x1ok) v11 = base[((size_t)((y0+1)*WW + x0 + 1))*PL + c];
            float val = v00*(1.f-wy)*(1.f-wx) + v01*(1.f-wy)*wx
                      + v10*wy*(1.f-wx)       + v11*wy*wx;
            s_sh[p*CK + c*9 + k] = val * mk;     // stride-9 writes: bank-conflict-free
        }
    }
    __syncthreads();

    // Phase B: deform matvec. thread: o = 4l..4l+3 (float4 weights), p = p0, p0+1.
    const int l  = tid & 31;
    const int p0 = (tid >> 5) * 2;
    float acc[8];
#pragma unroll
    for (int i = 0; i < 8; i++) acc[i] = 0.f;
    {
        const float* sp0 = s_sh + p0 * CK;
        const float* sp1 = sp0 + CK;
#pragma unroll 4
        for (int ck = 0; ck < CK; ck++) {
            float4 wv = *(const float4*)&g_wDcT[ck*PL + 4*l];
            float sa = sp0[ck], sb = sp1[ck];
            acc[0] += wv.x * sa; acc[1] += wv.y * sa; acc[2] += wv.z * sa; acc[3] += wv.w * sa;
            acc[4] += wv.x * sb; acc[5] += wv.y * sb; acc[6] += wv.z * sb; acc[7] += wv.w * sb;
        }
    }
    // bias + bn2 + relu -> v_sh
#pragma unroll
    for (int j = 0; j < 4; j++) {
        int o = 4*l + j;
        float bb = b_dc[o], ss = s2[o], tt = t2[o];
        v_sh[p0*PL + o]     = fmaxf((acc[j]     + bb) * ss + tt, 0.f);
        v_sh[(p0+1)*PL + o] = fmaxf((acc[4 + j] + bb) * ss + tt, 0.f);
    }
    __syncthreads();

    // Phase C: conv3 (1x1) + bn3a/relu + bn3b -> out_sh (reuses s_sh)
    float a3[8];
#pragma unroll
    for (int i = 0; i < 8; i++) a3[i] = 0.f;
    {
        const float* vp0 = v_sh + p0 * PL;
        const float* vp1 = vp0 + PL;
#pragma unroll 4
        for (int i = 0; i < PL; i++) {
            float4 wv = *(const float4*)&g_w3T[i*PL + 4*l];
            float va = vp0[i], vb = vp1[i];
            a3[0] += wv.x * va; a3[1] += wv.y * va; a3[2] += wv.z * va; a3[3] += wv.w * va;
            a3[4] += wv.x * vb; a3[5] += wv.y * vb; a3[6] += wv.z * vb; a3[7] += wv.w * vb;
        }
    }
    float* out_sh = s_sh;  // safe: all phase-B reads of s_sh finished before prior barrier
#pragma unroll
    for (int j = 0; j < 4; j++) {
        int o = 4*l + j;
        float sa = s3a[o], ta = t3a[o], sb = s3b[o], tb = t3b[o];
        out_sh[p0*PL + o]     = fmaxf(a3[j]     * sa + ta, 0.f) * sb + tb;
        out_sh[(p0+1)*PL + o] = fmaxf(a3[4 + j] * sa + ta, 0.f) * sb + tb;
    }
    __syncthreads();

    // Final: + identity, relu, NCHW store (each thread: one channel, 8 consecutive pos = full 32B sectors)
    {
        const int o2 = tid & 127;
        const int ph = tid >> 7;
        const float* idrow = g_ident + ((size_t)(b*PL + o2))*HW + pos0;
        float* orow = out + ((size_t)(b*PL + o2))*HW + pos0;
#pragma unroll
        for (int pp = 0; pp < 8; pp++) {
            int p = ph*8 + pp;
            orow[p] = fmaxf(out_sh[p*PL + o2] + idrow[p], 0.f);
        }
    }
}

// ---------------- host ----------------
extern "C" void kernel_launch(void* const* d_in, const int* in_sizes, int n_in,
                              void* d_out, int out_size) {
    const float* x    = (const float*)d_in[0];
    const float* w1   = (const float*)d_in[1];
    const float* s1a  = (const float*)d_in[2];
    const float* t1a  = (const float*)d_in[3];
    const float* s1b  = (const float*)d_in[4];
    const float* t1b  = (const float*)d_in[5];
    const float* w_off= (const float*)d_in[6];
    const float* b_off= (const float*)d_in[7];
    const float* w_dc = (const float*)d_in[8];
    const float* b_dc = (const float*)d_in[9];
    const float* s2   = (const float*)d_in[10];
    const float* t2   = (const float*)d_in[11];
    const float* w3   = (const float*)d_in[12];
    const float* s3a  = (const float*)d_in[13];
    const float* t3a  = (const float*)d_in[14];
    const float* s3b  = (const float*)d_in[15];
    const float* t3b  = (const float*)d_in[16];
    const float* w_ds = (const float*)d_in[17];
    const float* b_ds = (const float*)d_in[18];
    const float* sd   = (const float*)d_in[19];
    const float* td   = (const float*)d_in[20];
    float* out = (float*)d_out;

    k_prep<<<(CK*PL + 255)/256, 256>>>(w_off, w_dc, w3);

    dim3 g1(HW/64, 4, NB);
    k_conv1_ds<<<g1, 256>>>(x, w1, w_ds, s1a, t1a, s1b, t1b, b_ds, sd, td);

    dim3 g2(HH, NB);
    k_offset<<<g2, 128>>>(b_off);

    cudaFuncSetAttribute(k_deform, cudaFuncAttributeMaxDynamicSharedMemorySize, (int)SMEM3);
    dim3 g3(HW/16, NB);
    k_deform<<<g3, 256, SMEM3>>>(b_dc, s2, t2, s3a, t3a, s3b, t3b, out);
}

// round 3
// speedup vs baseline: 1.9311x; 1.9311x over previous
#include <cuda_runtime.h>
#include <cstdint>
#include <math.h>

#define NB  4
#define CIN 256
#define PL  128
#define HH  128
#define WW  128
#define HW  16384
#define KK  9
#define CK  1152   // PL*KK

// ---- scratch (device globals: allocation-free) ----
__device__ float g_out1_nchw[NB*PL*HW];
__device__ float g_out1_nhwc[NB*HW*PL];
__device__ float g_ident[NB*PL*HW];
__device__ float g_py[NB*KK*HW];
__device__ float g_px[NB*KK*HW];
__device__ float g_mk[NB*KK*HW];
__device__ float g_wOffT[CK*32];          // [ck][o<27, pad 32]
__device__ float g_wDcB[CK*PL];           // [k*128+c][o]
__device__ float g_w3T[PL*PL];            // [c][o]

// ---- packed f32x2 helpers (PTX-only; ptxas never auto-fuses) ----
__device__ __forceinline__ uint64_t pack2(float lo, float hi) {
    uint64_t r; asm("mov.b64 %0, {%1, %2};" : "=l"(r) : "f"(lo), "f"(hi)); return r;
}
__device__ __forceinline__ void unpack2(uint64_t v, float& lo, float& hi) {
    asm("mov.b64 {%0, %1}, %2;" : "=f"(lo), "=f"(hi) : "l"(v));
}
__device__ __forceinline__ void ffma2(uint64_t& d, uint64_t a, uint64_t b) {
    asm("fma.rn.f32x2 %0, %1, %2, %0;" : "+l"(d) : "l"(a), "l"(b));
}

// ---------------- K0: weight transposes ----------------
__global__ void k_prep(const float* __restrict__ w_off,
                       const float* __restrict__ w_dc,
                       const float* __restrict__ w3) {
    int i = blockIdx.x * blockDim.x + threadIdx.x;
    if (i < CK*32) {
        int ck = i >> 5, o = i & 31;
        g_wOffT[i] = (o < 27) ? w_off[o*CK + ck] : 0.f;
    }
    if (i < CK*PL) {
        int o = i & 127, t = i >> 7;
        int c = t & 127, k = t >> 7;
        g_wDcB[i] = w_dc[(o*PL + c)*KK + k];
    }
    if (i < PL*PL) {
        int c = i >> 7, o = i & 127;
        g_w3T[i] = w3[o*PL + c];
    }
}

// ---------------- K1: conv1(+bn+relu x2) and downsample ----------------
__global__ __launch_bounds__(256) void k_conv1_ds(
    const float* __restrict__ x, const float* __restrict__ w1, const float* __restrict__ wds,
    const float* __restrict__ s1a, const float* __restrict__ t1a,
    const float* __restrict__ s1b, const float* __restrict__ t1b,
    const float* __restrict__ bds, const float* __restrict__ sd, const float* __restrict__ td)
{
    __shared__ __align__(16) float sm[4352];
    float* Wsh = sm;          // [32][68]
    float* Xsh = sm + 2176;   // [32][68]

    const int t  = threadIdx.x;
    const int px = t & 15;
    const int oy = t >> 4;
    const int pos0 = blockIdx.x * 64;
    const int ot = blockIdx.y;
    const int b  = blockIdx.z;
    const bool isds = (ot >= 2);
    const float* w = isds ? wds : w1;
    const int o0 = (ot & 1) * 64;

    float acc[4][4];
#pragma unroll
    for (int j = 0; j < 4; j++)
#pragma unroll
        for (int k = 0; k < 4; k++) acc[j][k] = 0.f;

    const float* xb = x + (size_t)b * CIN * HW + pos0;

    for (int c0 = 0; c0 < CIN; c0 += 32) {
        for (int idx = t; idx < 2048; idx += 256) {
            int o = idx >> 5, i = idx & 31;
            Wsh[i*68 + o] = w[(o0 + o)*CIN + c0 + i];
        }
        for (int idx = t; idx < 2048; idx += 256) {
            int i = idx >> 6, p = idx & 63;
            Xsh[i*68 + p] = xb[(size_t)(c0 + i) * HW + p];
        }
        __syncthreads();
#pragma unroll
        for (int i = 0; i < 32; i++) {
            float4 wv = *(const float4*)&Wsh[i*68 + oy*4];
            float4 xv = *(const float4*)&Xsh[i*68 + px*4];
            float wr[4] = {wv.x, wv.y, wv.z, wv.w};
            float xr[4] = {xv.x, xv.y, xv.z, xv.w};
#pragma unroll
            for (int j = 0; j < 4; j++)
#pragma unroll
                for (int k = 0; k < 4; k++) acc[j][k] += wr[j] * xr[k];
        }
        __syncthreads();
    }

    if (!isds) {
#pragma unroll
        for (int j = 0; j < 4; j++) {
            int o = o0 + oy*4 + j;
            float sa = s1a[o], ta = t1a[o], sb = s1b[o], tb = t1b[o];
#pragma unroll
            for (int k = 0; k < 4; k++) {
                int p = pos0 + px*4 + k;
                float y = acc[j][k];
                y = fmaxf(y * sa + ta, 0.f);
                y = fmaxf(y * sb + tb, 0.f);
                g_out1_nchw[((size_t)(b*PL + o))*HW + p] = y;
                sm[(px*4 + k)*68 + oy*4 + j] = y;
            }
        }
        __syncthreads();
        for (int idx = t; idx < 4096; idx += 256) {
            int p = idx >> 6, o = idx & 63;
            g_out1_nhwc[((size_t)(b*HW + pos0 + p))*PL + o0 + o] = sm[p*68 + o];
        }
    } else {
#pragma unroll
        for (int j = 0; j < 4; j++) {
            int o = o0 + oy*4 + j;
            float bb = bds[o], ss = sd[o], tt = td[o];
#pragma unroll
            for (int k = 0; k < 4; k++) {
                int p = pos0 + px*4 + k;
                g_ident[((size_t)(b*PL + o))*HW + p] = (acc[j][k] + bb) * ss + tt;
            }
        }
    }
}

// ---------------- K2: offset/mask 3x3 conv ----------------
__global__ __launch_bounds__(128) void k_offset(const float* __restrict__ b_off) {
    const int t = threadIdx.x;
    const int lane = t & 31;
    const int h = blockIdx.x;
    const int b = blockIdx.y;
    const int xx = (t >> 5) * 32 + lane;

    float acc[28];
#pragma unroll
    for (int i = 0; i < 28; i++) acc[i] = 0.f;

    const float* inb = g_out1_nchw + (size_t)b * PL * HW;

    for (int c = 0; c < PL; c++) {
        const float* row = inb + (size_t)c * HW + h * WW;
        float sv[3][3];
#pragma unroll
        for (int dy = 0; dy < 3; dy++) {
            int yy = h + dy - 1;
            float m = 0.f, lf = 0.f, rg = 0.f;
            if (yy >= 0 && yy < HH) {
                const float* r2 = row + (dy - 1) * WW;
                m = r2[xx];
                lf = __shfl_up_sync(0xffffffffu, m, 1);
                if (lane == 0)  lf = (xx > 0) ? r2[xx - 1] : 0.f;
                rg = __shfl_down_sync(0xffffffffu, m, 1);
                if (lane == 31) rg = (xx < WW - 1) ? r2[xx + 1] : 0.f;
            }
            sv[dy][0] = lf; sv[dy][1] = m; sv[dy][2] = rg;
        }
#pragma unroll
        for (int k = 0; k < 9; k++) {
            float s = sv[k/3][k%3];
            const float4* wp = (const float4*)&g_wOffT[(c*9 + k) * 32];
#pragma unroll
            for (int j = 0; j < 7; j++) {
                float4 w4 = wp[j];
                acc[4*j+0] += w4.x * s;
                acc[4*j+1] += w4.y * s;
                acc[4*j+2] += w4.z * s;
                acc[4*j+3] += w4.w * s;
            }
        }
    }

    const int pos = h * WW + xx;
#pragma unroll
    for (int k = 0; k < 9; k++) {
        float dyv = acc[k]      + b_off[k];
        float dxv = acc[9 + k]  + b_off[9 + k];
        float z   = acc[18 + k] + b_off[18 + k];
        float mk  = 1.f / (1.f + expf(-z));
        int idx = (b*KK + k)*HW + pos;
        g_py[idx] = (float)(h - 1 + k/3) + dyv;
        g_px[idx] = (float)(xx - 1 + k%3) + dxv;
        g_mk[idx] = mk;
    }
}

// ---------------- K3: deform GEMM (f32x2) + bn2/relu + conv3 + bn3s + residual ----------------
// SMEM (floats):
//   A  double buf: [2][16][136]  @ 0      (4352)
//   B  double buf: [2][16][136]  @ 4352   (4352)
//   coords cY/cX/cM [1152] each  @ 8704   (3456)    total mainloop 12160 floats
//   V  [128][136]                @ 0      (17408)   (reuses A/B/coords after mainloop)
//   B2 [16][136]                 @ 17408  (2176)    total 19584 floats = 78336 B
#define LDP 136
#define SMF_A      0
#define SMF_B      4352
#define SMF_CY     8704
#define SMF_CX     (SMF_CY + 1152)
#define SMF_CM     (SMF_CX + 1152)
#define SMF_V      0
#define SMF_B2     17408
#define SMEM_TOT   (19584 * 4)

struct Stage { float a[8]; float4 b0, b1; };

__device__ __forceinline__ void gather8(const float* __restrict__ nhwc,
                                        const float* cY, const float* cX, const float* cM,
                                        int tap, int pos, int cbase, float st[8]) {
    int ci = tap*128 + pos;
    float py = cY[ci], px = cX[ci], mk = cM[ci];
    float fy = floorf(py), fx = floorf(px);
    float wy = py - fy, wx = px - fx;
    int y0 = (int)fy, x0 = (int)fx;
    bool y0k = ((unsigned)y0 < HH), y1k = ((unsigned)(y0+1) < HH);
    bool x0k = ((unsigned)x0 < WW), x1k = ((unsigned)(x0+1) < WW);
    float w00 = (1.f-wy)*(1.f-wx)*mk, w01 = (1.f-wy)*wx*mk;
    float w10 = wy*(1.f-wx)*mk,       w11 = wy*wx*mk;
    const float* p00 = nhwc + ((long)y0*WW + x0)*PL + cbase;
    float4 z = make_float4(0.f, 0.f, 0.f, 0.f);
    bool v00 = y0k && x0k, v01 = y0k && x1k, v10 = y1k && x0k, v11 = y1k && x1k;
    float4 q00a = v00 ? *(const float4*)p00 : z;
    float4 q00b = v00 ? *(const float4*)(p00 + 4) : z;
    float4 q01a = v01 ? *(const float4*)(p00 + PL) : z;
    float4 q01b = v01 ? *(const float4*)(p00 + PL + 4) : z;
    float4 q10a = v10 ? *(const float4*)(p00 + WW*PL) : z;
    float4 q10b = v10 ? *(const float4*)(p00 + WW*PL + 4) : z;
    float4 q11a = v11 ? *(const float4*)(p00 + WW*PL + PL) : z;
    float4 q11b = v11 ? *(const float4*)(p00 + WW*PL + PL + 4) : z;
    st[0] = q00a.x*w00 + q01a.x*w01 + q10a.x*w10 + q11a.x*w11;
    st[1] = q00a.y*w00 + q01a.y*w01 + q10a.y*w10 + q11a.y*w11;
    st[2] = q00a.z*w00 + q01a.z*w01 + q10a.z*w10 + q11a.z*w11;
    st[3] = q00a.w*w00 + q01a.w*w01 + q10a.w*w10 + q11a.w*w11;
    st[4] = q00b.x*w00 + q01b.x*w01 + q10b.x*w10 + q11b.x*w11;
    st[5] = q00b.y*w00 + q01b.y*w01 + q10b.y*w10 + q11b.y*w11;
    st[6] = q00b.z*w00 + q01b.z*w01 + q10b.z*w10 + q11b.z*w11;
    st[7] = q00b.w*w00 + q01b.w*w01 + q10b.w*w10 + q11b.w*w11;
}

__device__ __forceinline__ void compute16(const float* As, const float* Bs,
                                          int row0, int col0, uint64_t acc[4][8]) {
#pragma unroll
    for (int kk = 0; kk < 16; kk++) {
        float4 a0 = *(const float4*)&As[kk*LDP + row0];
        float4 a1 = *(const float4*)&As[kk*LDP + row0 + 4];
        float4 b0 = *(const float4*)&Bs[kk*LDP + col0];
        float4 b1 = *(const float4*)&Bs[kk*LDP + col0 + 4];
        uint64_t a2[4];
        a2[0] = pack2(a0.x, a0.y); a2[1] = pack2(a0.z, a0.w);
        a2[2] = pack2(a1.x, a1.y); a2[3] = pack2(a1.z, a1.w);
        float bj[8] = {b0.x, b0.y, b0.z, b0.w, b1.x, b1.y, b1.z, b1.w};
#pragma unroll
        for (int j = 0; j < 8; j++) {
            uint64_t b2 = pack2(bj[j], bj[j]);
#pragma unroll
            for (int i2 = 0; i2 < 4; i2++) ffma2(acc[i2][j], a2[i2], b2);
        }
    }
}

__global__ __launch_bounds__(256, 2) void k_dgemm(
    const float* __restrict__ b_dc, const float* __restrict__ s2, const float* __restrict__ t2,
    const float* __restrict__ s3a, const float* __restrict__ t3a,
    const float* __restrict__ s3b, const float* __restrict__ t3b,
    float* __restrict__ out)
{
    extern __shared__ __align__(16) float smf[];
    float* cY = smf + SMF_CY;
    float* cX = smf + SMF_CX;
    float* cM = smf + SMF_CM;

    const int tid  = threadIdx.x;
    const int row0 = (tid & 15) * 8;
    const int col0 = (tid >> 4) * 8;
    const int gpos = tid >> 1;            // gather position
    const int cg   = (tid & 1) * 8;       // gather channel sub-offset
    const int pos0 = blockIdx.x * 128;
    const int b    = pos0 >> 14;
    const int pim0 = pos0 & (HW - 1);

    // load coords
    for (int idx = tid; idx < 1152; idx += 256) {
        int k = idx >> 7, p = idx & 127;
        int gidx = (b*KK + k)*HW + pim0 + p;
        cY[idx] = g_py[gidx]; cX[idx] = g_px[gidx]; cM[idx] = g_mk[gidx];
    }
    __syncthreads();

    const float* nhwc = g_out1_nhwc + (size_t)b * HW * PL;

    // B-load indices (fixed per thread)
    const int f4 = tid * 2;
    const int bkk = f4 >> 5;
    const int bo4 = (f4 & 31) * 4;

    uint64_t acc[4][8];
    const uint64_t zz = pack2(0.f, 0.f);
#pragma unroll
    for (int i2 = 0; i2 < 4; i2++)
#pragma unroll
        for (int j = 0; j < 8; j++) acc[i2][j] = zz;

    Stage st;
    // prologue: chunk 0
    {
        gather8(nhwc, cY, cX, cM, 0, gpos, cg, st.a);
        const float* src = g_wDcB + (size_t)bkk * 128 + bo4;
        st.b0 = *(const float4*)src; st.b1 = *(const float4*)(src + 4);
        float* Ab = smf + SMF_A;
        float* Bb = smf + SMF_B;
#pragma unroll
        for (int j = 0; j < 8; j++) Ab[(cg + j)*LDP + gpos] = st.a[j];
        *(float4*)&Bb[bkk*LDP + bo4] = st.b0;
        *(float4*)&Bb[bkk*LDP + bo4 + 4] = st.b1;
    }
    __syncthreads();

    for (int kc = 0; kc < 72; kc++) {
        if (kc < 71) {
            int kn = kc + 1;
            gather8(nhwc, cY, cX, cM, kn >> 3, gpos, ((kn & 7) << 4) + cg, st.a);
            const float* src = g_wDcB + ((size_t)kn*16 + bkk)*128 + bo4;
            st.b0 = *(const float4*)src; st.b1 = *(const float4*)(src + 4);
        }
        compute16(smf + SMF_A + (kc & 1)*2176, smf + SMF_B + (kc & 1)*2176, row0, col0, acc);
        if (kc < 71) {
            float* Ab = smf + SMF_A + ((kc + 1) & 1)*2176;
            float* Bb = smf + SMF_B + ((kc + 1) & 1)*2176;
#pragma unroll
            for (int j = 0; j < 8; j++) Ab[(cg + j)*LDP + gpos] = st.a[j];
            *(float4*)&Bb[bkk*LDP + bo4] = st.b0;
            *(float4*)&Bb[bkk*LDP + bo4 + 4] = st.b1;
        }
        __syncthreads();
    }

    // epilogue 1: v = relu(bn2(acc + b_dc)) -> V[c][pos]  (V overlaps A/B/coords, all dead)
    float* Vs = smf + SMF_V;
#pragma unroll
    for (int j = 0; j < 8; j++) {
        int c = col0 + j;
        float bb = __ldg(b_dc + c), ss = __ldg(s2 + c), tt = __ldg(t2 + c);
#pragma unroll
        for (int i2 = 0; i2 < 4; i2++) {
            float v0, v1; unpack2(acc[i2][j], v0, v1);
            v0 = fmaxf((v0 + bb) * ss + tt, 0.f);
            v1 = fmaxf((v1 + bb) * ss + tt, 0.f);
            *(float2*)&Vs[c*LDP + row0 + 2*i2] = make_float2(v0, v1);
        }
    }

    // GEMM2: conv3 over K=128 in 8 chunks
    uint64_t acc3[4][8];
#pragma unroll
    for (int i2 = 0; i2 < 4; i2++)
#pragma unroll
        for (int j = 0; j < 8; j++) acc3[i2][j] = zz;

    float* B2 = smf + SMF_B2;
    for (int cb = 0; cb < 8; cb++) {
        const float* src = g_w3T + ((size_t)cb*16 + bkk)*128 + bo4;
        float4 r0 = *(const float4*)src;
        float4 r1 = *(const float4*)(src + 4);
        __syncthreads();   // previous compute (and V writes on cb==0) complete
        *(float4*)&B2[bkk*LDP + bo4] = r0;
        *(float4*)&B2[bkk*LDP + bo4 + 4] = r1;
        __syncthreads();
        compute16(Vs + cb*16*LDP, B2, row0, col0, acc3);
    }

    // epilogue 2: bn3a/relu/bn3b + identity + relu -> NCHW float4 stores
#pragma unroll
    for (int j = 0; j < 8; j++) {
        int c = col0 + j;
        float sa = __ldg(s3a + c), ta = __ldg(t3a + c);
        float sb = __ldg(s3b + c), tb = __ldg(t3b + c);
        float v[8];
#pragma unroll
        for (int i2 = 0; i2 < 4; i2++) {
            float v0, v1; unpack2(acc3[i2][j], v0, v1);
            v[2*i2]     = fmaxf(v0 * sa + ta, 0.f) * sb + tb;
            v[2*i2 + 1] = fmaxf(v1 * sa + ta, 0.f) * sb + tb;
        }
        size_t base = ((size_t)(b*PL + c))*HW + pim0 + row0;
        float4 id0 = *(const float4*)&g_ident[base];
        float4 id1 = *(const float4*)&g_ident[base + 4];
        float4 o0 = make_float4(fmaxf(v[0] + id0.x, 0.f), fmaxf(v[1] + id0.y, 0.f),
                                fmaxf(v[2] + id0.z, 0.f), fmaxf(v[3] + id0.w, 0.f));
        float4 o1 = make_float4(fmaxf(v[4] + id1.x, 0.f), fmaxf(v[5] + id1.y, 0.f),
                                fmaxf(v[6] + id1.z, 0.f), fmaxf(v[7] + id1.w, 0.f));
        *(float4*)&out[base] = o0;
        *(float4*)&out[base + 4] = o1;
    }
}

// ---------------- host ----------------
extern "C" void kernel_launch(void* const* d_in, const int* in_sizes, int n_in,
                              void* d_out, int out_size) {
    const float* x    = (const float*)d_in[0];
    const float* w1   = (const float*)d_in[1];
    const float* s1a  = (const float*)d_in[2];
    const float* t1a  = (const float*)d_in[3];
    const float* s1b  = (const float*)d_in[4];
    const float* t1b  = (const float*)d_in[5];
    const float* w_off= (const float*)d_in[6];
    const float* b_off= (const float*)d_in[7];
    const float* w_dc = (const float*)d_in[8];
    const float* b_dc = (const float*)d_in[9];
    const float* s2   = (const float*)d_in[10];
    const float* t2   = (const float*)d_in[11];
    const float* w3   = (const float*)d_in[12];
    const float* s3a  = (const float*)d_in[13];
    const float* t3a  = (const float*)d_in[14];
    const float* s3b  = (const float*)d_in[15];
    const float* t3b  = (const float*)d_in[16];
    const float* w_ds = (const float*)d_in[17];
    const float* b_ds = (const float*)d_in[18];
    const float* sd   = (const float*)d_in[19];
    const float* td   = (const float*)d_in[20];
    float* out = (float*)d_out;

    k_prep<<<(CK*PL + 255)/256, 256>>>(w_off, w_dc, w3);

    dim3 g1(HW/64, 4, NB);
    k_conv1_ds<<<g1, 256>>>(x, w1, w_ds, s1a, t1a, s1b, t1b, b_ds, sd, td);

    dim3 g2(HH, NB);
    k_offset<<<g2, 128>>>(b_off);

    cudaFuncSetAttribute(k_dgemm, cudaFuncAttributeMaxDynamicSharedMemorySize, SMEM_TOT);
    k_dgemm<<<NB*HW/128, 256, SMEM_TOT>>>(b_dc, s2, t2, s3a, t3a, s3b, t3b, out);
}